// round 16
// baseline (speedup 1.0000x reference)
#include <cuda_runtime.h>
#include <math.h>

typedef unsigned long long ull;

// ---------------------------------------------------------------------------
// Packed f32x2 helpers (convB only — measured fastest for L4)
// ---------------------------------------------------------------------------
__device__ __forceinline__ ull pk2(float lo, float hi) {
    ull r; asm("mov.b64 %0, {%1, %2};" : "=l"(r) : "f"(lo), "f"(hi)); return r;
}
__device__ __forceinline__ void upk2(ull v, float& lo, float& hi) {
    asm("mov.b64 {%0, %1}, %2;" : "=f"(lo), "=f"(hi) : "l"(v));
}
__device__ __forceinline__ void fma2(ull& d, ull a, ull b) {
    asm("fma.rn.f32x2 %0, %1, %2, %0;" : "+l"(d) : "l"(a), "l"(b));
}

// ---------------------------------------------------------------------------
// Intermediate activation buffers (device globals — no allocation allowed).
// ---------------------------------------------------------------------------
__device__ float g_a1[38880000];   // 256*3*15^4
__device__ float g_a2[15925248];   // 256*3*12^4
__device__ float g_a3[6718464];    // 256*4*9^4
__device__ float g_a4[1658880];    // 256*5*6^4
__device__ float g_a5[327680];     // 256*5*4^4  (== flattened [256,1280])

__host__ __device__ constexpr int slice_pitch(int s3) { return (s3 + 6) & ~1; }

// ===========================================================================
// convSD: R12's scalar conv with ONE change — double-buffered slice staging.
// Identical inner instruction stream; prefetch of slice idx+1 into buf^1
// overlaps compute on buf^0, and barriers drop from 2/stage to 1/stage.
// Dynamic SMEM: 2 * S3 floats. Weights in static SMEM as before.
// ===========================================================================
template<int CIN, int COUT, int K, int S, int TLOC, int NTHR, int MINB>
__global__ void __launch_bounds__(NTHR, MINB)
convSD(const float* __restrict__ in, float* __restrict__ out,
       const float* __restrict__ w, const float* __restrict__ bias)
{
    constexpr int O = S - K + 1, TCH = O / TLOC, NST = TLOC + K - 1;
    constexpr int S2 = S * S, S3 = S2 * S, S4 = S3 * S;
    constexpr int O2 = O * O, O3 = O2 * O;
    constexpr int KW4 = K * K * K * K;
    constexpr int NW = COUT * CIN * KW4;
    constexpr int NACT = TLOC * O2;
    constexpr int NSL = CIN * NST;

    extern __shared__ float dsm[];           // 2 * S3
    __shared__ float s_w[NW];

    const int bt = blockIdx.x, tchunk = bt % TCH, b = bt / TCH;
    const int t0 = tchunk * TLOC, tid = threadIdx.x;

    for (int i = tid; i < NW; i += NTHR) s_w[i] = w[i];

    const int tl = tid / O2, rem = tid - tl * O2, dd = rem / O, hh = rem - dd * O;
    const bool act = tid < NACT;

    float acc[COUT][O];
#pragma unroll
    for (int c = 0; c < COUT; c++)
#pragma unroll
        for (int r = 0; r < O; r++) acc[c][r] = 0.0f;

    {   // preload slice 0 into buffer 0
        const float* src = in + (size_t)b * CIN * S4 + (size_t)t0 * S3;
        for (int i = tid; i < S3; i += NTHR) dsm[i] = src[i];
    }

#pragma unroll 1
    for (int idx = 0; idx < NSL; idx++) {
        __syncthreads();   // buf^(idx&1) now complete; prior reads of buf^(idx+1&1) done
        if (idx + 1 < NSL) {   // prefetch next slice into the other buffer
            const int ci2 = (idx + 1) / NST, s2 = (idx + 1) - ci2 * NST;
            const float* src = in + (size_t)(b * CIN + ci2) * S4 + (size_t)(t0 + s2) * S3;
            float* dst = dsm + ((idx + 1) & 1) * S3;
            for (int i = tid; i < S3; i += NTHR) dst[i] = src[i];
        }

        const int ci = idx / NST, s = idx - ci * NST;
        const int kt = s - tl;
        if (act && kt >= 0 && kt < K) {
            const float* buf = dsm + (idx & 1) * S3;
            const float* wb = s_w + (ci * K + kt) * (K * K * K);
#pragma unroll 1
            for (int kd = 0; kd < K; kd++) {
#pragma unroll
                for (int kh = 0; kh < K; kh++) {
                    const float* rp = buf + (dd + kd) * S2 + (hh + kh) * S;
                    float row[S];
#pragma unroll
                    for (int x = 0; x < S; x++) row[x] = rp[x];

                    float wr[COUT][K];
#pragma unroll
                    for (int co = 0; co < COUT; co++)
#pragma unroll
                        for (int kw = 0; kw < K; kw++)
                            wr[co][kw] = wb[co * CIN * KW4 + (kd * K + kh) * K + kw];

#pragma unroll
                    for (int kw = 0; kw < K; kw++)
#pragma unroll
                        for (int r = 0; r < O; r++)
#pragma unroll
                            for (int co = 0; co < COUT; co++)
                                acc[co][r] = fmaf(wr[co][kw], row[r + kw], acc[co][r]);
                }
            }
        }
    }

    if (act) {
        const int t = t0 + tl;
#pragma unroll
        for (int co = 0; co < COUT; co++) {
            const float bv = bias[co];
            float* op = out + (size_t)(b * COUT + co) * ((size_t)O * O3)
                            + (size_t)t * O3 + (dd * O + hh) * O;
#pragma unroll
            for (int r = 0; r < O; r++)
                op[r] = fmaxf(acc[co][r] + bv, 0.0f);
        }
    }
}

// ===========================================================================
// convB (measured-fastest L4, unchanged): whole-volume FFMA2 conv.
// ===========================================================================
template<int CO, int K, int RP, int COS>
__device__ __forceinline__ void row_r2(const float* __restrict__ rsrc,
                                       const float* __restrict__ wq,
                                       ull (&acc)[CO][RP])
{
    constexpr int RL = 2 * RP + K - 1;
    float row[RL];
#pragma unroll
    for (int x = 0; x < RL; x++) row[x] = rsrc[x];

    constexpr int NE = RP + 1;
    constexpr int NO = RP + (K >= 4 ? 1 : 0);
    ull rowE[NE], rowO[NO];
#pragma unroll
    for (int j = 0; j < NE; j++) rowE[j] = pk2(row[2 * j], row[2 * j + 1]);
#pragma unroll
    for (int j = 0; j < NO; j++) rowO[j] = pk2(row[2 * j + 1], row[2 * j + 2]);

#pragma unroll
    for (int kw = 0; kw < K; kw++) {
#pragma unroll
        for (int co = 0; co < CO; co++) {
            const float wv = wq[co * COS + kw];
            const ull w2 = pk2(wv, wv);
#pragma unroll
            for (int j = 0; j < RP; j++) {
                const ull a = (kw & 1) ? rowO[(kw >> 1) + j] : rowE[(kw >> 1) + j];
                fma2(acc[co][j], a, w2);
            }
        }
    }
}

template<int CIN, int COUT, int K, int S, int NTHR>
__global__ void __launch_bounds__(NTHR)
convB(const float* __restrict__ in, float* __restrict__ out,
      const float* __restrict__ w, const float* __restrict__ bias)
{
    constexpr int O = S - K + 1;
    constexpr int S2 = S * S, S3 = S2 * S, S4 = S3 * S;
    constexpr int O2 = O * O, O3 = O2 * O, O4 = O * O3;
    constexpr int K4 = K * K * K * K, NW = COUT * CIN * K4;
    constexpr int NACT = O * O2;
    constexpr int RP = (O + 1) / 2;
    constexpr int VP = slice_pitch(S4);

    extern __shared__ float dsm[];           // 2 * VP
    __shared__ float s_w[NW];

    const int b = blockIdx.x, tid = threadIdx.x;
    for (int i = tid; i < NW; i += NTHR) s_w[i] = w[i];

    const int tl = tid / O2, rem = tid - tl * O2, dd = rem / O, hh = rem - dd * O;
    const bool act = tid < NACT;

    ull acc[COUT][RP];
#pragma unroll
    for (int c = 0; c < COUT; c++)
#pragma unroll
        for (int j = 0; j < RP; j++) acc[c][j] = 0ull;

    {
        const float* src = in + (size_t)b * CIN * S4;
        for (int i = tid; i < S4; i += NTHR) dsm[i] = src[i];
    }
#pragma unroll 1
    for (int ci = 0; ci < CIN; ci++) {
        __syncthreads();
        if (ci + 1 < CIN) {
            const float* src = in + ((size_t)b * CIN + ci + 1) * S4;
            float* dst = dsm + ((ci + 1) & 1) * VP;
            for (int i = tid; i < S4; i += NTHR) dst[i] = src[i];
        }
        if (act) {
            const float* buf = dsm + (ci & 1) * VP;
#pragma unroll 1
            for (int kt = 0; kt < K; kt++) {
#pragma unroll 1
                for (int kd = 0; kd < K; kd++) {
#pragma unroll
                    for (int kh = 0; kh < K; kh++) {
                        const float* rp_ = buf + (tl + kt) * S3 + (dd + kd) * S2 + (hh + kh) * S;
                        const float* wq  = s_w + (((ci * K + kt) * K + kd) * K + kh) * K;
                        row_r2<COUT, K, RP, CIN * K4>(rp_, wq, acc);
                    }
                }
            }
        }
    }

    if (act) {
#pragma unroll
        for (int co = 0; co < COUT; co++) {
            const float bv = bias[co];
            float* op = out + ((size_t)b * COUT + co) * (size_t)O4
                            + (size_t)tl * O3 + (dd * O + hh) * O;
#pragma unroll
            for (int j = 0; j < RP; j++) {
                float v0, v1; upk2(acc[co][j], v0, v1);
                op[2 * j] = fmaxf(v0 + bv, 0.0f);
                if (2 * j + 1 < O) op[2 * j + 1] = fmaxf(v1 + bv, 0.0f);
            }
        }
    }
}

// ---------------------------------------------------------------------------
// Fused FC1(1280->33) + ReLU + FC2(33->1) + sigmoid. One block per batch row.
// ---------------------------------------------------------------------------
__global__ void __launch_bounds__(64)
fc_head(const float* __restrict__ h,
        const float* __restrict__ fc1w, const float* __restrict__ fc1b,
        const float* __restrict__ fc2w, const float* __restrict__ fc2b,
        float* __restrict__ out)
{
    __shared__ float sh[1280];
    __shared__ float so[33];
    const int b = blockIdx.x;

    for (int i = threadIdx.x; i < 1280; i += 64) sh[i] = h[(size_t)b * 1280 + i];
    __syncthreads();

    const int co = threadIdx.x;
    if (co < 33) {
        float a = 0.0f;
        const float* wr = fc1w + co * 1280;
#pragma unroll 4
        for (int k = 0; k < 1280; k++) a = fmaf(sh[k], __ldg(&wr[k]), a);
        so[co] = fmaxf(a + fc1b[co], 0.0f);
    }
    __syncthreads();

    if (threadIdx.x == 0) {
        float z = fc2b[0];
#pragma unroll
        for (int j = 0; j < 33; j++) z = fmaf(so[j], __ldg(&fc2w[j]), z);
        out[b] = 1.0f / (1.0f + expf(-z));
    }
}

// ---------------------------------------------------------------------------
// Inputs (metadata order):
// 0:x 1:w1 2:b1 3:w2 4:b2 5:w3 6:b3 7:w4 8:b4 9:w5 10:b5
// 11:fc1_w 12:fc1_b 13:fc2_w 14:fc2_b    -> out: [B,1] float32
// ---------------------------------------------------------------------------
extern "C" void kernel_launch(void* const* d_in, const int* in_sizes, int n_in,
                              void* d_out, int out_size)
{
    const float* x   = (const float*)d_in[0];
    const float* w1  = (const float*)d_in[1];
    const float* b1  = (const float*)d_in[2];
    const float* w2  = (const float*)d_in[3];
    const float* b2  = (const float*)d_in[4];
    const float* w3  = (const float*)d_in[5];
    const float* b3  = (const float*)d_in[6];
    const float* w4  = (const float*)d_in[7];
    const float* b4  = (const float*)d_in[8];
    const float* w5  = (const float*)d_in[9];
    const float* b5  = (const float*)d_in[10];
    const float* f1w = (const float*)d_in[11];
    const float* f1b = (const float*)d_in[12];
    const float* f2w = (const float*)d_in[13];
    const float* f2b = (const float*)d_in[14];

    const int B = in_sizes[0] / (18 * 18 * 18 * 18);

    float *a1, *a2, *a3, *a4, *a5;
    cudaGetSymbolAddress((void**)&a1, g_a1);
    cudaGetSymbolAddress((void**)&a2, g_a2);
    cudaGetSymbolAddress((void**)&a3, g_a3);
    cudaGetSymbolAddress((void**)&a4, g_a4);
    cudaGetSymbolAddress((void**)&a5, g_a5);

    constexpr int SM1 = 2 * 18 * 18 * 18 * 4;                    // 46656 B
    constexpr int SM2 = 2 * 15 * 15 * 15 * 4;                    // 27000 B
    constexpr int SM3 = 2 * 12 * 12 * 12 * 4;                    // 13824 B
    constexpr int SM5L = 2 * 6 * 6 * 6 * 4;                      //  1728 B
    constexpr int SM4 = 2 * slice_pitch(9 * 9 * 9 * 9) * 4;      // 52528 B

    cudaFuncSetAttribute(convSD<1, 3, 4, 18, 1, 256, 2>,
                         cudaFuncAttributeMaxDynamicSharedMemorySize, SM1);
    cudaFuncSetAttribute(convSD<3, 3, 4, 15, 1, 256, 2>,
                         cudaFuncAttributeMaxDynamicSharedMemorySize, SM2);
    cudaFuncSetAttribute(convSD<3, 4, 4, 12, 3, 256, 2>,
                         cudaFuncAttributeMaxDynamicSharedMemorySize, SM3);
    cudaFuncSetAttribute(convSD<5, 5, 3, 6, 4, 128, 2>,
                         cudaFuncAttributeMaxDynamicSharedMemorySize, SM5L);
    cudaFuncSetAttribute(convB<4, 5, 4, 9, 224>,
                         cudaFuncAttributeMaxDynamicSharedMemorySize, SM4);

    // L1: 18^4 -> 15^4, 1->3, k=4   (R12 config + double-buffered staging)
    convSD<1, 3, 4, 18, 1, 256, 2><<<B * 15, 256, SM1>>>(x,  a1, w1, b1);
    // L2: 15^4 -> 12^4, 3->3, k=4   (R12 config + double-buffered staging)
    convSD<3, 3, 4, 15, 1, 256, 2><<<B * 12, 256, SM2>>>(a1, a2, w2, b2);
    // L3: 12^4 -> 9^4, 3->4, k=4    (R12 config + double-buffered staging)
    convSD<3, 4, 4, 12, 3, 256, 2><<<B * 3, 256, SM3>>>(a2, a3, w3, b3);
    // L4: 9^4 -> 6^4, 4->5, k=4     (convB, ~124us, ten measurements)
    convB<4, 5, 4, 9, 224><<<B, 224, SM4>>>(a3, a4, w4, b4);
    // L5: 6^4 -> 4^4, 5->5, k=3     (R12 config + double-buffered staging)
    convSD<5, 5, 3, 6, 4, 128, 2><<<B, 128, SM5L>>>(a4, a5, w5, b5);
    // FC head: [B,1280] -> [B,33] -> [B,1] sigmoid
    fc_head<<<B, 64>>>(a5, f1w, f1b, f2w, f2b, (float*)d_out);
}

// round 17
// speedup vs baseline: 1.1391x; 1.1391x over previous
#include <cuda_runtime.h>
#include <math.h>

typedef unsigned long long ull;

// ---------------------------------------------------------------------------
// Packed f32x2 helpers (convB only — measured fastest for L4)
// ---------------------------------------------------------------------------
__device__ __forceinline__ ull pk2(float lo, float hi) {
    ull r; asm("mov.b64 %0, {%1, %2};" : "=l"(r) : "f"(lo), "f"(hi)); return r;
}
__device__ __forceinline__ void upk2(ull v, float& lo, float& hi) {
    asm("mov.b64 {%0, %1}, %2;" : "=f"(lo), "=f"(hi) : "l"(v));
}
__device__ __forceinline__ void fma2(ull& d, ull a, ull b) {
    asm("fma.rn.f32x2 %0, %1, %2, %0;" : "+l"(d) : "l"(a), "l"(b));
}

// ---------------------------------------------------------------------------
// Intermediate activation buffers (device globals — no allocation allowed).
// ---------------------------------------------------------------------------
__device__ float g_a1[38880000];   // 256*3*15^4
__device__ float g_a2[15925248];   // 256*3*12^4
__device__ float g_a3[6718464];    // 256*4*9^4
__device__ float g_a4[1658880];    // 256*5*6^4
__device__ float g_a5[327680];     // 256*5*4^4  (== flattened [256,1280])

__host__ __device__ constexpr int slice_pitch(int s3) { return (s3 + 6) & ~1; }

// ---------------------------------------------------------------------------
// Auxiliary stream + fork/join events, created ONCE at static-init (host
// objects only — no device memory). Used to run two independent batch-half
// pipelines concurrently. If creation fails, we fall back to single-stream.
// ---------------------------------------------------------------------------
struct AuxStream {
    cudaStream_t s = nullptr;
    cudaEvent_t  f = nullptr, j = nullptr;
    bool ok = false;
    AuxStream() {
        if (cudaStreamCreateWithFlags(&s, cudaStreamNonBlocking) != cudaSuccess) return;
        if (cudaEventCreateWithFlags(&f, cudaEventDisableTiming) != cudaSuccess) return;
        if (cudaEventCreateWithFlags(&j, cudaEventDisableTiming) != cudaSuccess) return;
        ok = true;
    }
};
static AuxStream g_aux;

// ===========================================================================
// convS: the proven full-row scalar conv (+bias+ReLU). Block = (b, t-chunk).
// Thread = (t_local, d, h) computes the full W row for all COUT.
// BYTE-IDENTICAL to the banked R12 kernel.
// ===========================================================================
template<int CIN, int COUT, int K, int S, int TLOC, int NTHR>
__global__ void __launch_bounds__(NTHR)
convS(const float* __restrict__ in, float* __restrict__ out,
      const float* __restrict__ w, const float* __restrict__ bias)
{
    constexpr int O = S - K + 1, TCH = O / TLOC, NST = TLOC + K - 1;
    constexpr int S2 = S * S, S3 = S2 * S, S4 = S3 * S;
    constexpr int O2 = O * O, O3 = O2 * O;
    constexpr int KW4 = K * K * K * K;
    constexpr int NW = COUT * CIN * KW4;
    constexpr int NACT = TLOC * O2;

    __shared__ float s_slice[S3];
    __shared__ float s_w[NW];

    const int bt = blockIdx.x, tchunk = bt % TCH, b = bt / TCH;
    const int t0 = tchunk * TLOC, tid = threadIdx.x;

    for (int i = tid; i < NW; i += NTHR) s_w[i] = w[i];

    const int tl = tid / O2, rem = tid - tl * O2, dd = rem / O, hh = rem - dd * O;
    const bool act = tid < NACT;

    float acc[COUT][O];
#pragma unroll
    for (int c = 0; c < COUT; c++)
#pragma unroll
        for (int r = 0; r < O; r++) acc[c][r] = 0.0f;

#pragma unroll 1
    for (int ci = 0; ci < CIN; ci++) {
#pragma unroll 1
        for (int s = 0; s < NST; s++) {
            __syncthreads();
            const float* src = in + (size_t)(b * CIN + ci) * S4 + (size_t)(t0 + s) * S3;
            for (int i = tid; i < S3; i += NTHR) s_slice[i] = src[i];
            __syncthreads();

            const int kt = s - tl;
            if (act && kt >= 0 && kt < K) {
                const float* wb = s_w + (ci * K + kt) * (K * K * K);
#pragma unroll 1
                for (int kd = 0; kd < K; kd++) {
#pragma unroll
                    for (int kh = 0; kh < K; kh++) {
                        const float* rp = s_slice + (dd + kd) * S2 + (hh + kh) * S;
                        float row[S];
#pragma unroll
                        for (int x = 0; x < S; x++) row[x] = rp[x];

                        float wr[COUT][K];
#pragma unroll
                        for (int co = 0; co < COUT; co++)
#pragma unroll
                            for (int kw = 0; kw < K; kw++)
                                wr[co][kw] = wb[co * CIN * KW4 + (kd * K + kh) * K + kw];

#pragma unroll
                        for (int kw = 0; kw < K; kw++)
#pragma unroll
                            for (int r = 0; r < O; r++)
#pragma unroll
                                for (int co = 0; co < COUT; co++)
                                    acc[co][r] = fmaf(wr[co][kw], row[r + kw], acc[co][r]);
                    }
                }
            }
        }
    }

    if (act) {
        const int t = t0 + tl;
#pragma unroll
        for (int co = 0; co < COUT; co++) {
            const float bv = bias[co];
            float* op = out + (size_t)(b * COUT + co) * ((size_t)O * O3)
                            + (size_t)t * O3 + (dd * O + hh) * O;
#pragma unroll
            for (int r = 0; r < O; r++)
                op[r] = fmaxf(acc[co][r] + bv, 0.0f);
        }
    }
}

// ===========================================================================
// FFMA2 row engine (convB only) — BYTE-IDENTICAL to R12.
// ===========================================================================
template<int CO, int K, int RP, int COS>
__device__ __forceinline__ void row_r2(const float* __restrict__ rsrc,
                                       const float* __restrict__ wq,
                                       ull (&acc)[CO][RP])
{
    constexpr int RL = 2 * RP + K - 1;
    float row[RL];
#pragma unroll
    for (int x = 0; x < RL; x++) row[x] = rsrc[x];

    constexpr int NE = RP + 1;
    constexpr int NO = RP + (K >= 4 ? 1 : 0);
    ull rowE[NE], rowO[NO];
#pragma unroll
    for (int j = 0; j < NE; j++) rowE[j] = pk2(row[2 * j], row[2 * j + 1]);
#pragma unroll
    for (int j = 0; j < NO; j++) rowO[j] = pk2(row[2 * j + 1], row[2 * j + 2]);

#pragma unroll
    for (int kw = 0; kw < K; kw++) {
#pragma unroll
        for (int co = 0; co < CO; co++) {
            const float wv = wq[co * COS + kw];
            const ull w2 = pk2(wv, wv);
#pragma unroll
            for (int j = 0; j < RP; j++) {
                const ull a = (kw & 1) ? rowO[(kw >> 1) + j] : rowE[(kw >> 1) + j];
                fma2(acc[co][j], a, w2);
            }
        }
    }
}

// ===========================================================================
// convB (measured-fastest L4, unchanged): whole-volume FFMA2 conv.
// ===========================================================================
template<int CIN, int COUT, int K, int S, int NTHR>
__global__ void __launch_bounds__(NTHR)
convB(const float* __restrict__ in, float* __restrict__ out,
      const float* __restrict__ w, const float* __restrict__ bias)
{
    constexpr int O = S - K + 1;
    constexpr int S2 = S * S, S3 = S2 * S, S4 = S3 * S;
    constexpr int O2 = O * O, O3 = O2 * O, O4 = O * O3;
    constexpr int K4 = K * K * K * K, NW = COUT * CIN * K4;
    constexpr int NACT = O * O2;
    constexpr int RP = (O + 1) / 2;
    constexpr int VP = slice_pitch(S4);

    extern __shared__ float dsm[];           // 2 * VP
    __shared__ float s_w[NW];

    const int b = blockIdx.x, tid = threadIdx.x;
    for (int i = tid; i < NW; i += NTHR) s_w[i] = w[i];

    const int tl = tid / O2, rem = tid - tl * O2, dd = rem / O, hh = rem - dd * O;
    const bool act = tid < NACT;

    ull acc[COUT][RP];
#pragma unroll
    for (int c = 0; c < COUT; c++)
#pragma unroll
        for (int j = 0; j < RP; j++) acc[c][j] = 0ull;

    {
        const float* src = in + (size_t)b * CIN * S4;
        for (int i = tid; i < S4; i += NTHR) dsm[i] = src[i];
    }
#pragma unroll 1
    for (int ci = 0; ci < CIN; ci++) {
        __syncthreads();
        if (ci + 1 < CIN) {
            const float* src = in + ((size_t)b * CIN + ci + 1) * S4;
            float* dst = dsm + ((ci + 1) & 1) * VP;
            for (int i = tid; i < S4; i += NTHR) dst[i] = src[i];
        }
        if (act) {
            const float* buf = dsm + (ci & 1) * VP;
#pragma unroll 1
            for (int kt = 0; kt < K; kt++) {
#pragma unroll 1
                for (int kd = 0; kd < K; kd++) {
#pragma unroll
                    for (int kh = 0; kh < K; kh++) {
                        const float* rp_ = buf + (tl + kt) * S3 + (dd + kd) * S2 + (hh + kh) * S;
                        const float* wq  = s_w + (((ci * K + kt) * K + kd) * K + kh) * K;
                        row_r2<COUT, K, RP, CIN * K4>(rp_, wq, acc);
                    }
                }
            }
        }
    }

    if (act) {
#pragma unroll
        for (int co = 0; co < COUT; co++) {
            const float bv = bias[co];
            float* op = out + ((size_t)b * COUT + co) * (size_t)O4
                            + (size_t)tl * O3 + (dd * O + hh) * O;
#pragma unroll
            for (int j = 0; j < RP; j++) {
                float v0, v1; upk2(acc[co][j], v0, v1);
                op[2 * j] = fmaxf(v0 + bv, 0.0f);
                if (2 * j + 1 < O) op[2 * j + 1] = fmaxf(v1 + bv, 0.0f);
            }
        }
    }
}

// ---------------------------------------------------------------------------
// Fused FC1(1280->33) + ReLU + FC2(33->1) + sigmoid. One block per batch row.
// ---------------------------------------------------------------------------
__global__ void __launch_bounds__(64)
fc_head(const float* __restrict__ h,
        const float* __restrict__ fc1w, const float* __restrict__ fc1b,
        const float* __restrict__ fc2w, const float* __restrict__ fc2b,
        float* __restrict__ out)
{
    __shared__ float sh[1280];
    __shared__ float so[33];
    const int b = blockIdx.x;

    for (int i = threadIdx.x; i < 1280; i += 64) sh[i] = h[(size_t)b * 1280 + i];
    __syncthreads();

    const int co = threadIdx.x;
    if (co < 33) {
        float a = 0.0f;
        const float* wr = fc1w + co * 1280;
#pragma unroll 4
        for (int k = 0; k < 1280; k++) a = fmaf(sh[k], __ldg(&wr[k]), a);
        so[co] = fmaxf(a + fc1b[co], 0.0f);
    }
    __syncthreads();

    if (threadIdx.x == 0) {
        float z = fc2b[0];
#pragma unroll
        for (int j = 0; j < 33; j++) z = fmaf(so[j], __ldg(&fc2w[j]), z);
        out[b] = 1.0f / (1.0f + expf(-z));
    }
}

// ---------------------------------------------------------------------------
// Inputs (metadata order):
// 0:x 1:w1 2:b1 3:w2 4:b2 5:w3 6:b3 7:w4 8:b4 9:w5 10:b5
// 11:fc1_w 12:fc1_b 13:fc2_w 14:fc2_b    -> out: [B,1] float32
// ---------------------------------------------------------------------------
extern "C" void kernel_launch(void* const* d_in, const int* in_sizes, int n_in,
                              void* d_out, int out_size)
{
    const float* x   = (const float*)d_in[0];
    const float* w1  = (const float*)d_in[1];
    const float* b1  = (const float*)d_in[2];
    const float* w2  = (const float*)d_in[3];
    const float* b2  = (const float*)d_in[4];
    const float* w3  = (const float*)d_in[5];
    const float* b3  = (const float*)d_in[6];
    const float* w4  = (const float*)d_in[7];
    const float* b4  = (const float*)d_in[8];
    const float* w5  = (const float*)d_in[9];
    const float* b5  = (const float*)d_in[10];
    const float* f1w = (const float*)d_in[11];
    const float* f1b = (const float*)d_in[12];
    const float* f2w = (const float*)d_in[13];
    const float* f2b = (const float*)d_in[14];

    const int B = in_sizes[0] / (18 * 18 * 18 * 18);

    float *a1, *a2, *a3, *a4, *a5;
    cudaGetSymbolAddress((void**)&a1, g_a1);
    cudaGetSymbolAddress((void**)&a2, g_a2);
    cudaGetSymbolAddress((void**)&a3, g_a3);
    cudaGetSymbolAddress((void**)&a4, g_a4);
    cudaGetSymbolAddress((void**)&a5, g_a5);

    constexpr int SM4 = 2 * slice_pitch(9 * 9 * 9 * 9) * 4;      // 52528 B
    cudaFuncSetAttribute(convB<4, 5, 4, 9, 224>,
                         cudaFuncAttributeMaxDynamicSharedMemorySize, SM4);

    // per-batch element strides
    constexpr size_t ST_X  = 18 * 18 * 18 * 18;   // 104976
    constexpr size_t ST_A1 = 3 * 15 * 15 * 15 * 15;
    constexpr size_t ST_A2 = 3 * 12 * 12 * 12 * 12;
    constexpr size_t ST_A3 = 4 * 9 * 9 * 9 * 9;
    constexpr size_t ST_A4 = 5 * 6 * 6 * 6 * 6;
    constexpr size_t ST_A5 = 5 * 4 * 4 * 4 * 4;   // 1280

    // Launch the full 6-kernel pipeline for `n` batch elements starting at
    // element offset `off`, on stream `st` (R12-identical kernels/configs).
    auto launch_pipe = [&](int off, int n, cudaStream_t st) {
        const float* xc  = x  + (size_t)off * ST_X;
        float* a1c = a1 + (size_t)off * ST_A1;
        float* a2c = a2 + (size_t)off * ST_A2;
        float* a3c = a3 + (size_t)off * ST_A3;
        float* a4c = a4 + (size_t)off * ST_A4;
        float* a5c = a5 + (size_t)off * ST_A5;
        float* oc  = (float*)d_out + off;

        convS<1, 3, 4, 18, 1, 256><<<n * 15, 256, 0, st>>>(xc,  a1c, w1, b1);
        convS<3, 3, 4, 15, 1, 256><<<n * 12, 256, 0, st>>>(a1c, a2c, w2, b2);
        convS<3, 4, 4, 12, 3, 256><<<n * 3,  256, 0, st>>>(a2c, a3c, w3, b3);
        convB<4, 5, 4, 9, 224><<<n, 224, SM4, st>>>(a3c, a4c, w4, b4);
        convS<5, 5, 3, 6, 4, 128><<<n, 128, 0, st>>>(a4c, a5c, w5, b5);
        fc_head<<<n, 64, 0, st>>>(a5c, f1w, f1b, f2w, f2b, oc);
    };

    if (g_aux.ok && B >= 2) {
        const int H = B / 2;
        const int R = B - H;
        // fork: aux stream joins the (captured) default stream's timeline
        cudaEventRecord(g_aux.f, 0);
        cudaStreamWaitEvent(g_aux.s, g_aux.f, 0);
        // two independent batch-half pipelines, overlapped
        launch_pipe(0, H, 0);
        launch_pipe(H, R, g_aux.s);
        // join: default stream waits for aux pipeline completion
        cudaEventRecord(g_aux.j, g_aux.s);
        cudaStreamWaitEvent(0, g_aux.j, 0);
    } else {
        // fallback: banked single-stream R12 configuration
        launch_pipe(0, B, 0);
    }
}